// round 16
// baseline (speedup 1.0000x reference)
#include <cuda_runtime.h>
#include <cuda_fp16.h>
#include <cstdint>
#include <cfloat>

#define NN   50000
#define FF   128
#define H1   4
#define C1   64
#define HC1  256     // H1*C1
#define C2   64
#define EE   400000
#define ETOT (EE + NN)

// ---------------- scratch (static __device__, no allocs) ----------------
__device__ __align__(16) __half g_xh [(size_t)NN * FF];   // x (fp16)
__device__ __align__(16) __half g_xs1[(size_t)NN * HC1];  // x @ W1t (fp16)
__device__ __align__(16) __half g_h  [(size_t)NN * HC1];  // hidden (fp16)
__device__ __align__(16) __half g_xs2[(size_t)NN * C2];   // h @ W2t (fp16)
__device__ __align__(16) float g_as1[NN * H1];
__device__ __align__(16) float g_ad1[NN * H1];
__device__ __align__(16) float g_as2[NN];
__device__ __align__(16) float g_ad2[NN];
__device__ __align__(16) float g_v1src[FF * H1];
__device__ __align__(16) float g_v1dst[FF * H1];
__device__ __align__(16) float g_v2src[HC1];
__device__ __align__(16) float g_v2dst[HC1];
__device__ __align__(16) int   g_src[ETOT];
__device__ __align__(16) int   g_dst[ETOT];
__device__ __align__(16) int   g_deg[NN];    // zeroed by fused2 tail (BSS-zero first run)
__device__ __align__(16) int   g_cnt[NN];    // zeroed by k_scan
__device__ __align__(16) int   g_off[NN + 1];
__device__ __align__(16) int   g_csr[ETOT];
// transposed fp16 weights: [N, K] row-major
__device__ __align__(16) __half g_w1[HC1 * FF];    // [256,128]
__device__ __align__(16) __half g_w2[C2 * HC1];    // [64,256]

// ---------------- helpers ----------------
__device__ __forceinline__ float lrelu(float v) { return v > 0.f ? v : 0.2f * v; }

__device__ __forceinline__ uint32_t su32(const void* p) {
    return (uint32_t)__cvta_generic_to_shared(p);
}
__device__ __forceinline__ uint32_t pk(__half a, __half b) {
    __half2 t(a, b);
    return *(uint32_t*)&t;
}
__device__ __forceinline__ void ldsm4(uint32_t& r0, uint32_t& r1, uint32_t& r2, uint32_t& r3,
                                      uint32_t addr) {
    asm volatile("ldmatrix.sync.aligned.m8n8.x4.shared.b16 {%0,%1,%2,%3}, [%4];"
                 : "=r"(r0), "=r"(r1), "=r"(r2), "=r"(r3) : "r"(addr));
}
__device__ __forceinline__ void mma16816(float* c, const uint32_t* a, uint32_t b0, uint32_t b1) {
    asm volatile("mma.sync.aligned.m16n8k16.row.col.f32.f16.f16.f32 "
                 "{%0,%1,%2,%3}, {%4,%5,%6,%7}, {%8,%9}, {%0,%1,%2,%3};"
                 : "+f"(c[0]), "+f"(c[1]), "+f"(c[2]), "+f"(c[3])
                 : "r"(a[0]), "r"(a[1]), "r"(a[2]), "r"(a[3]), "r"(b0), "r"(b1));
}

// ---------------- decode (inline dtype detection) + degree histogram ----------
__global__ void k_decode(const void* __restrict__ ei) {
    __shared__ int s32;
    if (threadIdx.x < 32) {
        const int* p = (const int*)ei;
        int nz = 0;
        #pragma unroll
        for (int j = 0; j < 4; j++) nz |= p[2 * (threadIdx.x * 4 + j) + 1];
        unsigned any = __ballot_sync(0xffffffffu, nz != 0);
        if (threadIdx.x == 0) s32 = (any != 0u) ? 1 : 0;
    }
    __syncthreads();
    int e = blockIdx.x * blockDim.x + threadIdx.x;
    if (e >= ETOT) return;
    int s, d;
    if (e < EE) {
        if (s32) {
            const int* p = (const int*)ei;
            s = p[e]; d = p[EE + e];
        } else {
            const long long* p = (const long long*)ei;
            s = (int)p[e]; d = (int)p[EE + e];
        }
    } else {
        s = e - EE; d = s;
    }
    g_src[e] = s; g_dst[e] = d;
    atomicAdd(&g_deg[d], 1);
}

// single-block exclusive scan of g_deg -> g_off; also zeroes g_cnt
__global__ void k_scan() {
    __shared__ int wsum[32];
    const int T = 1024;
    const int CH = (NN + T - 1) / T;
    int t = threadIdx.x;
    int lane = t & 31, w = t >> 5;
    int base = t * CH;
    int sum = 0;
    for (int i = 0; i < CH; i++) { int idx = base + i; if (idx < NN) sum += g_deg[idx]; }
    int v = sum;
    #pragma unroll
    for (int o = 1; o < 32; o <<= 1) {
        int u = __shfl_up_sync(0xffffffffu, v, o);
        if (lane >= o) v += u;
    }
    if (lane == 31) wsum[w] = v;
    __syncthreads();
    if (w == 0) {
        int u = wsum[lane];
        #pragma unroll
        for (int o = 1; o < 32; o <<= 1) {
            int q = __shfl_up_sync(0xffffffffu, u, o);
            if (lane >= o) u += q;
        }
        wsum[lane] = u;
    }
    __syncthreads();
    int ex = v - sum + (w ? wsum[w - 1] : 0);
    for (int i = 0; i < CH; i++) {
        int idx = base + i;
        if (idx < NN) { g_off[idx] = ex; ex += g_deg[idx]; g_cnt[idx] = 0; }
    }
    if (t == 0) g_off[NN] = ETOT;
}

__global__ void k_fill() {
    int e = blockIdx.x * blockDim.x + threadIdx.x;
    if (e >= ETOT) return;
    int d = g_dst[e];
    int pos = g_off[d] + atomicAdd(&g_cnt[d], 1);
    g_csr[pos] = g_src[e];
}

// ---------------- fold att vectors (WIDE: one warp per output scalar) ----------
// 1536 dot-products of length 64: [0,512) v1src, [512,1024) v1dst,
// [1024,1280) v2src, [1280,1536) v2dst.  192 blocks x 8 warps.
__global__ void k_fold(const float* __restrict__ W1s, const float* __restrict__ a1s,
                       const float* __restrict__ W1d, const float* __restrict__ a1d,
                       const float* __restrict__ W2s, const float* __restrict__ a2s,
                       const float* __restrict__ W2d, const float* __restrict__ a2d) {
    int W = blockIdx.x * 8 + (threadIdx.x >> 5);
    int lane = threadIdx.x & 31;
    float p = 0.f;
    if (W < 1024) {
        int o = W & 511;
        int f = o >> 2, h = o & 3;
        const float* Wm = (W < 512) ? W1s : W1d;
        const float* av = (W < 512) ? a1s : a1d;
        int b0 = h * C1 + lane;
        p = Wm[f * HC1 + b0] * av[b0] + Wm[f * HC1 + b0 + 32] * av[b0 + 32];
    } else {
        int t = W & 255;
        const float* Wm = (W < 1280) ? W2s : W2d;
        const float* av = (W < 1280) ? a2s : a2d;
        p = Wm[t * C2 + lane] * av[lane] + Wm[t * C2 + lane + 32] * av[lane + 32];
    }
    #pragma unroll
    for (int o = 16; o > 0; o >>= 1) p += __shfl_xor_sync(0xffffffffu, p, o);
    if (lane == 0) {
        if (W < 512)       g_v1src[(W >> 2) * H1 + (W & 3)] = p;
        else if (W < 1024) g_v1dst[((W - 512) >> 2) * H1 + (W & 3)] = p;
        else if (W < 1280) g_v2src[W - 1024] = p;
        else               g_v2dst[W - 1280] = p;
    }
}

// ---------------- fused prep: x->fp16 (+fp32 layer-1 scores), W transpose -------
#define XB ((NN + 31) / 32)     // 1563 blocks; warp = 4 rows, lane-group of 8 = 1 row
__global__ void k_pre(const float* __restrict__ x,
                      const float* __restrict__ W1s, const float* __restrict__ W2s) {
    int b = blockIdx.x;
    if (b < XB) {
        int lane = threadIdx.x & 31, w = threadIdx.x >> 5;
        int row = b * 32 + w * 4 + (lane >> 3);
        int c16 = (lane & 7) * 16;               // feature base (16 features/thread)
        float4 vv[4];
        if (row < NN) {
            const float4* xr = (const float4*)&x[(size_t)row * FF + c16];
            #pragma unroll
            for (int q = 0; q < 4; q++) vv[q] = xr[q];
            uint4 o0, o1;
            o0.x = pk(__float2half(vv[0].x), __float2half(vv[0].y));
            o0.y = pk(__float2half(vv[0].z), __float2half(vv[0].w));
            o0.z = pk(__float2half(vv[1].x), __float2half(vv[1].y));
            o0.w = pk(__float2half(vv[1].z), __float2half(vv[1].w));
            o1.x = pk(__float2half(vv[2].x), __float2half(vv[2].y));
            o1.y = pk(__float2half(vv[2].z), __float2half(vv[2].w));
            o1.z = pk(__float2half(vv[3].x), __float2half(vv[3].y));
            o1.w = pk(__float2half(vv[3].z), __float2half(vv[3].w));
            *(uint4*)&g_xh[(size_t)row * FF + c16]     = o0;
            *(uint4*)&g_xh[(size_t)row * FF + c16 + 8] = o1;
        }
        float s[4] = {0, 0, 0, 0}, d[4] = {0, 0, 0, 0};
        if (row < NN) {
            #pragma unroll
            for (int q = 0; q < 4; q++) {
                #pragma unroll
                for (int j = 0; j < 4; j++) {
                    int f = c16 + q * 4 + j;
                    float xf = (j == 0) ? vv[q].x : (j == 1) ? vv[q].y
                             : (j == 2) ? vv[q].z : vv[q].w;
                    float4 vs = *(const float4*)&g_v1src[f * H1];
                    float4 vd = *(const float4*)&g_v1dst[f * H1];
                    s[0] += xf * vs.x; s[1] += xf * vs.y; s[2] += xf * vs.z; s[3] += xf * vs.w;
                    d[0] += xf * vd.x; d[1] += xf * vd.y; d[2] += xf * vd.z; d[3] += xf * vd.w;
                }
            }
        }
        #pragma unroll
        for (int o = 1; o < 8; o <<= 1) {
            #pragma unroll
            for (int h = 0; h < 4; h++) {
                s[h] += __shfl_xor_sync(0xffffffffu, s[h], o);
                d[h] += __shfl_xor_sync(0xffffffffu, d[h], o);
            }
        }
        if ((lane & 7) == 0 && row < NN) {
            *(float4*)&g_as1[row * H1] = make_float4(s[0], s[1], s[2], s[3]);
            *(float4*)&g_ad1[row * H1] = make_float4(d[0], d[1], d[2], d[3]);
        }
    } else if (b < XB + 128) {                   // W1t [256,128]
        int i = (b - XB) * 256 + threadIdx.x;
        int n = i >> 7, k = i & 127;
        g_w1[i] = __float2half(W1s[(size_t)k * HC1 + n]);
    } else {                                     // W2t [64,256]
        int i = (b - XB - 128) * 256 + threadIdx.x;
        int n = i >> 8, k = i & 255;
        g_w2[i] = __float2half(W2s[(size_t)k * C2 + n]);
    }
}

// ---------------- pure fp16 HMMA GEMM: C[M,N_TOTAL] = A[M,K] @ Bt[N,K]^T --------
template <int K_TOTAL, int N_TOTAL>
__global__ __launch_bounds__(256)
void k_hmma(const __half* __restrict__ A, const __half* __restrict__ B,
            __half* __restrict__ C, int M) {
    constexpr int KC = 128;
    constexpr int NCH = K_TOTAL / KC;
    constexpr int RS = 272;                        // smem row stride bytes
    constexpr uint32_t A_OFF = 0;
    constexpr uint32_t B_OFF = 128u * RS;          // total 192*272 = 52224 B

    extern __shared__ char sm[];
    const uint32_t base = su32(sm);

    const int tid = threadIdx.x, l = tid & 31, w = tid >> 5;
    const int wm = w & 3, wn = w >> 2;             // 4 x 2 warp grid
    const int row0 = blockIdx.y * 128;
    const int col0 = blockIdx.x * 64;

    const uint32_t aOff = (uint32_t)((wm * 32 + (l & 15)) * RS + (l >> 4) * 16);
    const uint32_t bOff = (uint32_t)((wn * 32 + ((l >> 4) & 1) * 8 + (l & 7)) * RS
                                     + ((l >> 3) & 1) * 16);

    float acc[2][4][4];
    #pragma unroll
    for (int mt = 0; mt < 2; mt++)
        #pragma unroll
        for (int nt = 0; nt < 4; nt++)
            #pragma unroll
            for (int q = 0; q < 4; q++) acc[mt][nt][q] = 0.f;

    for (int ch = 0; ch < NCH; ch++) {
        #pragma unroll
        for (int j = 0; j < 16; j++) {
            int idx = j * 256 + tid;               // 4-fp16 chunk in [128 x 32]
            int r = idx >> 5, c4 = (idx & 31) * 4;
            int gr = row0 + r;
            uint2 v = make_uint2(0u, 0u);
            if (gr < M) v = *(const uint2*)&A[(size_t)gr * K_TOTAL + ch * KC + c4];
            *(uint2*)(sm + A_OFF + r * RS + c4 * 2) = v;
        }
        #pragma unroll
        for (int j = 0; j < 8; j++) {
            int idx = j * 256 + tid;               // 4-fp16 chunk in [64 x 32]
            int r = idx >> 5, c4 = (idx & 31) * 4;
            *(uint2*)(sm + B_OFF + r * RS + c4 * 2) =
                *(const uint2*)&B[(size_t)(col0 + r) * K_TOTAL + ch * KC + c4];
        }
        __syncthreads();

        #pragma unroll
        for (int ks = 0; ks < 8; ks++) {
            uint32_t ar[2][4], br[2][4];
            #pragma unroll
            for (int mt = 0; mt < 2; mt++)
                ldsm4(ar[mt][0], ar[mt][1], ar[mt][2], ar[mt][3],
                      base + A_OFF + aOff + mt * 16 * RS + ks * 32);
            #pragma unroll
            for (int np = 0; np < 2; np++)
                ldsm4(br[np][0], br[np][1], br[np][2], br[np][3],
                      base + B_OFF + bOff + np * 16 * RS + ks * 32);
            #pragma unroll
            for (int mt = 0; mt < 2; mt++)
                #pragma unroll
                for (int nt = 0; nt < 4; nt++)
                    mma16816(acc[mt][nt], ar[mt],
                             br[nt >> 1][(nt & 1) * 2], br[nt >> 1][(nt & 1) * 2 + 1]);
        }
        __syncthreads();
    }

    unsigned* C32 = (unsigned*)C;
    #pragma unroll
    for (int mt = 0; mt < 2; mt++)
        #pragma unroll
        for (int nt = 0; nt < 4; nt++) {
            int m0 = row0 + wm * 32 + mt * 16 + (l >> 2);
            int n  = col0 + wn * 32 + nt * 8 + (l & 3) * 2;
            if (m0 < M)
                C32[((size_t)m0 * N_TOTAL + n) >> 1] =
                    pk(__float2half(acc[mt][nt][0]), __float2half(acc[mt][nt][1]));
            if (m0 + 8 < M)
                C32[((size_t)(m0 + 8) * N_TOTAL + n) >> 1] =
                    pk(__float2half(acc[mt][nt][2]), __float2half(acc[mt][nt][3]));
        }
}

// ---------------- fused layer-1: softmax(m=0) + aggregate + bias/relu + L2 scores -
__global__ void k_fused1(const float* __restrict__ b1) {
    int node = (blockIdx.x * blockDim.x + threadIdx.x) >> 5;
    int lane = threadIdx.x & 31;
    if (node >= NN) return;
    int beg = g_off[node], end = g_off[node + 1];

    int head = lane >> 3;
    int col0 = lane * 8;
    float adh = g_ad1[node * H1 + head];

    float den = 0.f;
    float acc[8];
    #pragma unroll
    for (int j = 0; j < 8; j++) acc[j] = 0.f;

    #pragma unroll 4
    for (int i = beg; i < end; i++) {
        int s = g_csr[i];
        float ex = __expf(lrelu(g_as1[s * H1 + head] + adh));
        den += ex;
        uint4 v = *(const uint4*)&g_xs1[(size_t)s * HC1 + col0];   // 8 fp16
        float2 p0 = __half22float2(*(__half2*)&v.x);
        float2 p1 = __half22float2(*(__half2*)&v.y);
        float2 p2 = __half22float2(*(__half2*)&v.z);
        float2 p3 = __half22float2(*(__half2*)&v.w);
        acc[0] += ex * p0.x; acc[1] += ex * p0.y;
        acc[2] += ex * p1.x; acc[3] += ex * p1.y;
        acc[4] += ex * p2.x; acc[5] += ex * p2.y;
        acc[6] += ex * p3.x; acc[7] += ex * p3.y;
    }
    float inv = 1.f / den;
    float hrow[8];
    #pragma unroll
    for (int j = 0; j < 8; j++) hrow[j] = fmaxf(acc[j] * inv + b1[col0 + j], 0.f);

    uint4 hv;
    hv.x = pk(__float2half(hrow[0]), __float2half(hrow[1]));
    hv.y = pk(__float2half(hrow[2]), __float2half(hrow[3]));
    hv.z = pk(__float2half(hrow[4]), __float2half(hrow[5]));
    hv.w = pk(__float2half(hrow[6]), __float2half(hrow[7]));
    *(uint4*)&g_h[(size_t)node * HC1 + col0] = hv;

    // layer-2 scores from registers (fp32)
    float ps = 0.f, pd = 0.f;
    #pragma unroll
    for (int j = 0; j < 8; j++) {
        ps += hrow[j] * g_v2src[col0 + j];
        pd += hrow[j] * g_v2dst[col0 + j];
    }
    #pragma unroll
    for (int o = 16; o > 0; o >>= 1) {
        ps += __shfl_xor_sync(0xffffffffu, ps, o);
        pd += __shfl_xor_sync(0xffffffffu, pd, o);
    }
    if (lane == 0) { g_as2[node] = ps; g_ad2[node] = pd; }
}

// ---------------- fused layer-2: softmax(m=0) + aggregate + bias; re-zero deg ----
__global__ void k_fused2(float* __restrict__ out, const float* __restrict__ b2) {
    int gz = blockIdx.x * blockDim.x + threadIdx.x;
    if (gz < NN) g_deg[gz] = 0;                  // self-restore for next graph replay
    int node = gz >> 5;
    int lane = threadIdx.x & 31;
    if (node >= NN) return;
    int beg = g_off[node], end = g_off[node + 1];
    float adn = g_ad2[node];

    int col = lane * 2;
    float den = 0.f, a0 = 0.f, a1 = 0.f;
    #pragma unroll 4
    for (int i = beg; i < end; i++) {
        int s = g_csr[i];
        float ex = __expf(lrelu(g_as2[s] + adn));
        den += ex;
        float2 v = __half22float2(*(const __half2*)&g_xs2[(size_t)s * C2 + col]);
        a0 += ex * v.x; a1 += ex * v.y;
    }
    float inv = 1.f / den;
    *(float2*)&out[(size_t)node * C2 + col] =
        make_float2(a0 * inv + b2[col], a1 * inv + b2[col + 1]);
}

// ---------------- launcher ----------------
extern "C" void kernel_launch(void* const* d_in, const int* in_sizes, int n_in,
                              void* d_out, int out_size) {
    const float* x    = (const float*)d_in[0];
    const void*  ei   = d_in[1];
    const float* W1s  = (const float*)d_in[2];
    const float* W1d  = (const float*)d_in[3];
    const float* a1s  = (const float*)d_in[4];
    const float* a1d  = (const float*)d_in[5];
    const float* b1   = (const float*)d_in[6];
    const float* W2s  = (const float*)d_in[7];
    const float* W2d  = (const float*)d_in[8];
    const float* a2s  = (const float*)d_in[9];
    const float* a2d  = (const float*)d_in[10];
    const float* b2   = (const float*)d_in[11];
    float* out = (float*)d_out;

    cudaStream_t st = 0;

    constexpr int SMEM_MMA = 192 * 272;    // 52224 B -> 4 CTAs/SM
    constexpr int NT = (NN + 127) / 128;   // 391 M-tiles

    static cudaStream_t s_side = nullptr;
    static cudaEvent_t  ev_fork = nullptr, ev_join = nullptr;
    if (!s_side) {
        cudaStreamCreateWithFlags(&s_side, cudaStreamNonBlocking);
        cudaEventCreateWithFlags(&ev_fork, cudaEventDisableTiming);
        cudaEventCreateWithFlags(&ev_join, cudaEventDisableTiming);
        cudaFuncSetAttribute(k_hmma<128, HC1>,
                             cudaFuncAttributeMaxDynamicSharedMemorySize, SMEM_MMA);
        cudaFuncSetAttribute(k_hmma<256, C2>,
                             cudaFuncAttributeMaxDynamicSharedMemorySize, SMEM_MMA);
    }

    void *p_xh, *p_xs1, *p_h, *p_xs2, *p_w1, *p_w2;
    cudaGetSymbolAddress(&p_xh,  g_xh);
    cudaGetSymbolAddress(&p_xs1, g_xs1);
    cudaGetSymbolAddress(&p_h,   g_h);
    cudaGetSymbolAddress(&p_xs2, g_xs2);
    cudaGetSymbolAddress(&p_w1,  g_w1);
    cudaGetSymbolAddress(&p_w2,  g_w2);

    // ---- fork: CSR chain on side stream; fold + prep + GEMM1 on main ----
    cudaEventRecord(ev_fork, st);
    cudaStreamWaitEvent(s_side, ev_fork, 0);

    int eb = (ETOT + 255) / 256;
    k_decode<<<eb, 256, 0, s_side>>>(ei);
    k_scan<<<1, 1024, 0, s_side>>>();
    k_fill<<<eb, 256, 0, s_side>>>();
    cudaEventRecord(ev_join, s_side);

    k_fold<<<192, 256, 0, st>>>(W1s, a1s, W1d, a1d, W2s, a2s, W2d, a2d);
    k_pre<<<XB + 192, 256, 0, st>>>(x, W1s, W2s);

    // xs1 = x @ W1t   [50000,128] x [128,256] -> fp16
    {
        dim3 grid(HC1 / 64, NT);
        k_hmma<128, HC1><<<grid, 256, SMEM_MMA, st>>>(
            (const __half*)p_xh, (const __half*)p_w1, (__half*)p_xs1, NN);
    }

    cudaStreamWaitEvent(st, ev_join, 0);   // join before fused1

    int nb = (NN * 32 + 255) / 256;
    k_fused1<<<nb, 256, 0, st>>>(b1);

    // xs2 = h @ W2t   [50000,256] x [256,64] -> fp16
    {
        dim3 grid(C2 / 64, NT);
        k_hmma<256, C2><<<grid, 256, SMEM_MMA, st>>>(
            (const __half*)p_h, (const __half*)p_w2, (__half*)p_xs2, NN);
    }

    k_fused2<<<nb, 256, 0, st>>>(out, b2);
}

// round 17
// speedup vs baseline: 1.2949x; 1.2949x over previous
#include <cuda_runtime.h>
#include <cuda_fp16.h>
#include <cstdint>
#include <cfloat>

#define NN   50000
#define FF   128
#define H1   4
#define C1   64
#define HC1  256     // H1*C1
#define C2   64
#define EE   400000
#define ETOT (EE + NN)

#define XS1S 264     // xs1ext row stride (256 data + 4 as + 4 ad)
#define XS2S 72      // xs2ext row stride (64 data + as2 + ad2 + pad)
#define W1R  320     // g_w1 rows (264 used, padded)
#define W2R  128     // g_w2 rows (66 used, padded)

// ---------------- scratch (static __device__, no allocs) ----------------
__device__ __align__(16) __half g_xh [(size_t)NN * FF];   // x (fp16)
__device__ __align__(16) __half g_xs1[(size_t)NN * XS1S]; // x @ W1ext (fp16)
__device__ __align__(16) __half g_h  [(size_t)NN * HC1];  // hidden (fp16)
__device__ __align__(16) __half g_xs2[(size_t)NN * XS2S]; // h @ W2ext (fp16)
__device__ __align__(16) int   g_src[ETOT];
__device__ __align__(16) int   g_dst[ETOT];
__device__ __align__(16) int   g_deg[NN];    // zeroed by fused2 tail (BSS-zero first run)
__device__ __align__(16) int   g_cnt[NN];    // zeroed by k_scan
__device__ __align__(16) int   g_off[NN + 1];
__device__ __align__(16) int   g_csr[ETOT];
// transposed fp16 weights (+ folded score rows): [N, K] row-major, zero-padded rows
__device__ __align__(16) __half g_w1[W1R * FF];    // rows 0..255 W1t, 256..259 v1src, 260..263 v1dst
__device__ __align__(16) __half g_w2[W2R * HC1];   // rows 0..63 W2t, 64 v2src, 65 v2dst

// ---------------- helpers ----------------
__device__ __forceinline__ float lrelu(float v) { return v > 0.f ? v : 0.2f * v; }

__device__ __forceinline__ uint32_t su32(const void* p) {
    return (uint32_t)__cvta_generic_to_shared(p);
}
__device__ __forceinline__ uint32_t pk(__half a, __half b) {
    __half2 t(a, b);
    return *(uint32_t*)&t;
}
__device__ __forceinline__ void ldsm4(uint32_t& r0, uint32_t& r1, uint32_t& r2, uint32_t& r3,
                                      uint32_t addr) {
    asm volatile("ldmatrix.sync.aligned.m8n8.x4.shared.b16 {%0,%1,%2,%3}, [%4];"
                 : "=r"(r0), "=r"(r1), "=r"(r2), "=r"(r3) : "r"(addr));
}
__device__ __forceinline__ void mma16816(float* c, const uint32_t* a, uint32_t b0, uint32_t b1) {
    asm volatile("mma.sync.aligned.m16n8k16.row.col.f32.f16.f16.f32 "
                 "{%0,%1,%2,%3}, {%4,%5,%6,%7}, {%8,%9}, {%0,%1,%2,%3};"
                 : "+f"(c[0]), "+f"(c[1]), "+f"(c[2]), "+f"(c[3])
                 : "r"(a[0]), "r"(a[1]), "r"(a[2]), "r"(a[3]), "r"(b0), "r"(b1));
}

// ---------------- decode (inline dtype detection) + degree histogram -------
__global__ void k_decode(const void* __restrict__ ei) {
    __shared__ int s32;
    if (threadIdx.x < 32) {
        const int* p = (const int*)ei;
        int nz = 0;
        #pragma unroll
        for (int j = 0; j < 4; j++) nz |= p[2 * (threadIdx.x * 4 + j) + 1];
        unsigned any = __ballot_sync(0xffffffffu, nz != 0);
        if (threadIdx.x == 0) s32 = (any != 0u) ? 1 : 0;
    }
    __syncthreads();
    int e = blockIdx.x * blockDim.x + threadIdx.x;
    if (e >= ETOT) return;
    int s, d;
    if (e < EE) {
        if (s32) {
            const int* p = (const int*)ei;
            s = p[e]; d = p[EE + e];
        } else {
            const long long* p = (const long long*)ei;
            s = (int)p[e]; d = (int)p[EE + e];
        }
    } else {
        s = e - EE; d = s;
    }
    g_src[e] = s; g_dst[e] = d;
    atomicAdd(&g_deg[d], 1);
}

// single-block exclusive scan of g_deg -> g_off; also zeroes g_cnt for k_fill
__global__ void k_scan() {
    __shared__ int wsum[32];
    const int T = 1024;
    const int CH = (NN + T - 1) / T;
    int t = threadIdx.x;
    int lane = t & 31, w = t >> 5;
    int base = t * CH;
    int sum = 0;
    for (int i = 0; i < CH; i++) { int idx = base + i; if (idx < NN) sum += g_deg[idx]; }
    int v = sum;
    #pragma unroll
    for (int o = 1; o < 32; o <<= 1) {
        int u = __shfl_up_sync(0xffffffffu, v, o);
        if (lane >= o) v += u;
    }
    if (lane == 31) wsum[w] = v;
    __syncthreads();
    if (w == 0) {
        int u = wsum[lane];
        #pragma unroll
        for (int o = 1; o < 32; o <<= 1) {
            int q = __shfl_up_sync(0xffffffffu, u, o);
            if (lane >= o) u += q;
        }
        wsum[lane] = u;
    }
    __syncthreads();
    int ex = v - sum + (w ? wsum[w - 1] : 0);
    for (int i = 0; i < CH; i++) {
        int idx = base + i;
        if (idx < NN) { g_off[idx] = ex; ex += g_deg[idx]; g_cnt[idx] = 0; }
    }
    if (t == 0) g_off[NN] = ETOT;
}

__global__ void k_fill() {
    int e = blockIdx.x * blockDim.x + threadIdx.x;
    if (e >= ETOT) return;
    int d = g_dst[e];
    int pos = g_off[d] + atomicAdd(&g_cnt[d], 1);
    g_csr[pos] = g_src[e];
}

// ---------------- fused prep: x->fp16 (vectorized), W transpose, att folds ------
#define XPB ((NN + 31) / 32)    // 1563 blocks: warp = 4 rows, 8 lanes/row, 16 floats/lane
__global__ void k_pre(const float* __restrict__ x,
                      const float* __restrict__ W1s, const float* __restrict__ a1s,
                      const float* __restrict__ W1d, const float* __restrict__ a1d,
                      const float* __restrict__ W2s, const float* __restrict__ a2s,
                      const float* __restrict__ W2d, const float* __restrict__ a2d) {
    int b = blockIdx.x;
    if (b < XPB) {                               // x convert, 64 B/thread
        int lane = threadIdx.x & 31, w = threadIdx.x >> 5;
        int row = b * 32 + w * 4 + (lane >> 3);
        if (row >= NN) return;
        int c16 = (lane & 7) * 16;
        const float4* xr = (const float4*)&x[(size_t)row * FF + c16];
        float4 v0 = xr[0], v1 = xr[1], v2 = xr[2], v3 = xr[3];
        uint4 o0, o1;
        o0.x = pk(__float2half(v0.x), __float2half(v0.y));
        o0.y = pk(__float2half(v0.z), __float2half(v0.w));
        o0.z = pk(__float2half(v1.x), __float2half(v1.y));
        o0.w = pk(__float2half(v1.z), __float2half(v1.w));
        o1.x = pk(__float2half(v2.x), __float2half(v2.y));
        o1.y = pk(__float2half(v2.z), __float2half(v2.w));
        o1.z = pk(__float2half(v3.x), __float2half(v3.y));
        o1.w = pk(__float2half(v3.z), __float2half(v3.w));
        *(uint4*)&g_xh[(size_t)row * FF + c16]     = o0;
        *(uint4*)&g_xh[(size_t)row * FF + c16 + 8] = o1;
    } else if (b < XPB + 128) {                  // W1t rows 0..255
        int i = (b - XPB) * 256 + threadIdx.x;
        int n = i >> 7, k = i & 127;
        g_w1[i] = __float2half(W1s[(size_t)k * HC1 + n]);
    } else if (b < XPB + 192) {                  // W2t rows 0..63
        int i = (b - XPB - 128) * 256 + threadIdx.x;
        int n = i >> 8, k = i & 255;
        g_w2[i] = __float2half(W2s[(size_t)k * C2 + n]);
    } else if (b < XPB + 194) {                  // v1 folds -> W1t rows 256..263
        int i = (b - XPB - 192) * 256 + threadIdx.x;  // 0..511
        int f = i >> 2, h = i & 3;
        float ss = 0.f, sd = 0.f;
        #pragma unroll 8
        for (int c = 0; c < C1; c++) {
            ss += W1s[f * HC1 + h * C1 + c] * a1s[h * C1 + c];
            sd += W1d[f * HC1 + h * C1 + c] * a1d[h * C1 + c];
        }
        g_w1[(256 + h) * FF + f] = __float2half(ss);
        g_w1[(260 + h) * FF + f] = __float2half(sd);
    } else {                                     // v2 folds -> W2t rows 64..65
        int t = threadIdx.x;                     // 0..255
        float ss = 0.f, sd = 0.f;
        #pragma unroll 8
        for (int c = 0; c < C2; c++) {
            ss += W2s[t * C2 + c] * a2s[c];
            sd += W2d[t * C2 + c] * a2d[c];
        }
        g_w2[64 * HC1 + t] = __float2half(ss);
        g_w2[65 * HC1 + t] = __float2half(sd);
    }
}

// ---------------- pure fp16 HMMA GEMM: C[M, N_STRIDE] = A[M,K] @ Bt[.,K]^T --------
// CTA tile 128x64, 8 warps (4M x 2N). grid.x covers ceil(N_STRIDE/64);
// B has >= grid.x*64 zero-padded rows. Writeback guarded to N_STRIDE.
template <int K_TOTAL, int N_STRIDE>
__global__ __launch_bounds__(256)
void k_hmma(const __half* __restrict__ A, const __half* __restrict__ B,
            __half* __restrict__ C, int M) {
    constexpr int KC = 128;
    constexpr int NCH = K_TOTAL / KC;
    constexpr int RS = 272;                        // smem row stride bytes
    constexpr uint32_t A_OFF = 0;
    constexpr uint32_t B_OFF = 128u * RS;          // total 192*272 = 52224 B

    extern __shared__ char sm[];
    const uint32_t base = su32(sm);

    const int tid = threadIdx.x, l = tid & 31, w = tid >> 5;
    const int wm = w & 3, wn = w >> 2;             // 4 x 2 warp grid
    const int row0 = blockIdx.y * 128;
    const int col0 = blockIdx.x * 64;

    const uint32_t aOff = (uint32_t)((wm * 32 + (l & 15)) * RS + (l >> 4) * 16);
    const uint32_t bOff = (uint32_t)((wn * 32 + ((l >> 4) & 1) * 8 + (l & 7)) * RS
                                     + ((l >> 3) & 1) * 16);

    float acc[2][4][4];
    #pragma unroll
    for (int mt = 0; mt < 2; mt++)
        #pragma unroll
        for (int nt = 0; nt < 4; nt++)
            #pragma unroll
            for (int q = 0; q < 4; q++) acc[mt][nt][q] = 0.f;

    for (int ch = 0; ch < NCH; ch++) {
        #pragma unroll
        for (int j = 0; j < 16; j++) {
            int idx = j * 256 + tid;               // 4-fp16 chunk in [128 x 32]
            int r = idx >> 5, c4 = (idx & 31) * 4;
            int gr = row0 + r;
            uint2 v = make_uint2(0u, 0u);
            if (gr < M) v = *(const uint2*)&A[(size_t)gr * K_TOTAL + ch * KC + c4];
            *(uint2*)(sm + A_OFF + r * RS + c4 * 2) = v;
        }
        #pragma unroll
        for (int j = 0; j < 8; j++) {
            int idx = j * 256 + tid;               // 4-fp16 chunk in [64 x 32]
            int r = idx >> 5, c4 = (idx & 31) * 4;
            *(uint2*)(sm + B_OFF + r * RS + c4 * 2) =
                *(const uint2*)&B[(size_t)(col0 + r) * K_TOTAL + ch * KC + c4];
        }
        __syncthreads();

        #pragma unroll
        for (int ks = 0; ks < 8; ks++) {
            uint32_t ar[2][4], br[2][4];
            #pragma unroll
            for (int mt = 0; mt < 2; mt++)
                ldsm4(ar[mt][0], ar[mt][1], ar[mt][2], ar[mt][3],
                      base + A_OFF + aOff + mt * 16 * RS + ks * 32);
            #pragma unroll
            for (int np = 0; np < 2; np++)
                ldsm4(br[np][0], br[np][1], br[np][2], br[np][3],
                      base + B_OFF + bOff + np * 16 * RS + ks * 32);
            #pragma unroll
            for (int mt = 0; mt < 2; mt++)
                #pragma unroll
                for (int nt = 0; nt < 4; nt++)
                    mma16816(acc[mt][nt], ar[mt],
                             br[nt >> 1][(nt & 1) * 2], br[nt >> 1][(nt & 1) * 2 + 1]);
        }
        __syncthreads();
    }

    // ---- writeback (fp16 pairs, guarded to N_STRIDE) ----
    unsigned* C32 = (unsigned*)C;
    #pragma unroll
    for (int mt = 0; mt < 2; mt++)
        #pragma unroll
        for (int nt = 0; nt < 4; nt++) {
            int m0 = row0 + wm * 32 + mt * 16 + (l >> 2);
            int n  = col0 + wn * 32 + nt * 8 + (l & 3) * 2;
            if (n < N_STRIDE) {
                if (m0 < M)
                    C32[((size_t)m0 * N_STRIDE + n) >> 1] =
                        pk(__float2half(acc[mt][nt][0]), __float2half(acc[mt][nt][1]));
                if (m0 + 8 < M)
                    C32[((size_t)(m0 + 8) * N_STRIDE + n) >> 1] =
                        pk(__float2half(acc[mt][nt][2]), __float2half(acc[mt][nt][3]));
            }
        }
}

// ---------------- fused layer-1: softmax(m=0) + aggregate + bias/relu -------------
__global__ void k_fused1(const float* __restrict__ b1) {
    int node = (blockIdx.x * blockDim.x + threadIdx.x) >> 5;
    int lane = threadIdx.x & 31;
    if (node >= NN) return;
    int beg = g_off[node], end = g_off[node + 1];

    int head = lane >> 3;
    int col0 = lane * 8;
    float adh = __half2float(g_xs1[(size_t)node * XS1S + 260 + head]);

    float den = 0.f;
    float acc[8];
    #pragma unroll
    for (int j = 0; j < 8; j++) acc[j] = 0.f;

    #pragma unroll 4
    for (int i = beg; i < end; i++) {
        int s = g_csr[i];
        float as = __half2float(g_xs1[(size_t)s * XS1S + 256 + head]);
        float ex = __expf(lrelu(as + adh));
        den += ex;
        uint4 v = *(const uint4*)&g_xs1[(size_t)s * XS1S + col0];   // 8 fp16
        float2 p0 = __half22float2(*(__half2*)&v.x);
        float2 p1 = __half22float2(*(__half2*)&v.y);
        float2 p2 = __half22float2(*(__half2*)&v.z);
        float2 p3 = __half22float2(*(__half2*)&v.w);
        acc[0] += ex * p0.x; acc[1] += ex * p0.y;
        acc[2] += ex * p1.x; acc[3] += ex * p1.y;
        acc[4] += ex * p2.x; acc[5] += ex * p2.y;
        acc[6] += ex * p3.x; acc[7] += ex * p3.y;
    }
    float inv = 1.f / den;
    float hrow[8];
    #pragma unroll
    for (int j = 0; j < 8; j++) hrow[j] = fmaxf(acc[j] * inv + b1[col0 + j], 0.f);

    uint4 hv;
    hv.x = pk(__float2half(hrow[0]), __float2half(hrow[1]));
    hv.y = pk(__float2half(hrow[2]), __float2half(hrow[3]));
    hv.z = pk(__float2half(hrow[4]), __float2half(hrow[5]));
    hv.w = pk(__float2half(hrow[6]), __float2half(hrow[7]));
    *(uint4*)&g_h[(size_t)node * HC1 + col0] = hv;
}

// ---------------- fused layer-2: softmax(m=0) + aggregate + bias; re-zero deg ----
__global__ void k_fused2(float* __restrict__ out, const float* __restrict__ b2) {
    int gz = blockIdx.x * blockDim.x + threadIdx.x;
    if (gz < NN) g_deg[gz] = 0;                  // self-restore for next graph replay
    int node = gz >> 5;
    int lane = threadIdx.x & 31;
    if (node >= NN) return;
    int beg = g_off[node], end = g_off[node + 1];
    float adn = __half2float(g_xs2[(size_t)node * XS2S + 65]);

    int col = lane * 2;
    float den = 0.f, a0 = 0.f, a1 = 0.f;
    #pragma unroll 4
    for (int i = beg; i < end; i++) {
        int s = g_csr[i];
        float as = __half2float(g_xs2[(size_t)s * XS2S + 64]);
        float ex = __expf(lrelu(as + adn));
        den += ex;
        float2 v = __half22float2(*(const __half2*)&g_xs2[(size_t)s * XS2S + col]);
        a0 += ex * v.x; a1 += ex * v.y;
    }
    float inv = 1.f / den;
    *(float2*)&out[(size_t)node * C2 + col] =
        make_float2(a0 * inv + b2[col], a1 * inv + b2[col + 1]);
}

// ---------------- launcher ----------------
extern "C" void kernel_launch(void* const* d_in, const int* in_sizes, int n_in,
                              void* d_out, int out_size) {
    const float* x    = (const float*)d_in[0];
    const void*  ei   = d_in[1];
    const float* W1s  = (const float*)d_in[2];
    const float* W1d  = (const float*)d_in[3];
    const float* a1s  = (const float*)d_in[4];
    const float* a1d  = (const float*)d_in[5];
    const float* b1   = (const float*)d_in[6];
    const float* W2s  = (const float*)d_in[7];
    const float* W2d  = (const float*)d_in[8];
    const float* a2s  = (const float*)d_in[9];
    const float* a2d  = (const float*)d_in[10];
    const float* b2   = (const float*)d_in[11];
    float* out = (float*)d_out;

    cudaStream_t st = 0;

    constexpr int SMEM_MMA = 192 * 272;    // 52224 B -> 4 CTAs/SM
    constexpr int NT = (NN + 127) / 128;   // 391 M-tiles

    static cudaStream_t s_side = nullptr;
    static cudaEvent_t  ev_fork = nullptr, ev_join = nullptr;
    if (!s_side) {
        cudaStreamCreateWithFlags(&s_side, cudaStreamNonBlocking);
        cudaEventCreateWithFlags(&ev_fork, cudaEventDisableTiming);
        cudaEventCreateWithFlags(&ev_join, cudaEventDisableTiming);
        cudaFuncSetAttribute(k_hmma<128, XS1S>,
                             cudaFuncAttributeMaxDynamicSharedMemorySize, SMEM_MMA);
        cudaFuncSetAttribute(k_hmma<256, XS2S>,
                             cudaFuncAttributeMaxDynamicSharedMemorySize, SMEM_MMA);
    }

    void *p_xh, *p_xs1, *p_h, *p_xs2, *p_w1, *p_w2;
    cudaGetSymbolAddress(&p_xh,  g_xh);
    cudaGetSymbolAddress(&p_xs1, g_xs1);
    cudaGetSymbolAddress(&p_h,   g_h);
    cudaGetSymbolAddress(&p_xs2, g_xs2);
    cudaGetSymbolAddress(&p_w1,  g_w1);
    cudaGetSymbolAddress(&p_w2,  g_w2);

    // ---- fork: CSR chain on side stream; prep + GEMM1 on main ----
    cudaEventRecord(ev_fork, st);
    cudaStreamWaitEvent(s_side, ev_fork, 0);

    int eb = (ETOT + 255) / 256;
    k_decode<<<eb, 256, 0, s_side>>>(ei);
    k_scan<<<1, 1024, 0, s_side>>>();
    k_fill<<<eb, 256, 0, s_side>>>();
    cudaEventRecord(ev_join, s_side);

    k_pre<<<XPB + 195, 256, 0, st>>>(x, W1s, a1s, W1d, a1d, W2s, a2s, W2d, a2d);

    // xs1ext = x @ W1ext   [50000,128] x [128,264] -> fp16 (incl as1/ad1 cols)
    {
        dim3 grid((XS1S + 63) / 64, NT);   // 5 x 391
        k_hmma<128, XS1S><<<grid, 256, SMEM_MMA, st>>>(
            (const __half*)p_xh, (const __half*)p_w1, (__half*)p_xs1, NN);
    }

    cudaStreamWaitEvent(st, ev_join, 0);   // join before fused1

    int nb = (NN * 32 + 255) / 256;
    k_fused1<<<nb, 256, 0, st>>>(b1);

    // xs2ext = h @ W2ext   [50000,256] x [256,66->72] -> fp16 (incl as2/ad2 cols)
    {
        dim3 grid((XS2S + 63) / 64, NT);   // 2 x 391
        k_hmma<256, XS2S><<<grid, 256, SMEM_MMA, st>>>(
            (const __half*)p_h, (const __half*)p_w2, (__half*)p_xs2, NN);
    }

    k_fused2<<<nb, 256, 0, st>>>(out, b2);
}